// round 12
// baseline (speedup 1.0000x reference)
#include <cuda_runtime.h>
#include <cstdint>

constexpr int NB = 4, C = 32, H = 512, W = 960, Ht = 128, Wt = 240, HW = H * W;
constexpr int SEG  = 320;    // pixels per block (one thread per pixel)
constexpr int BLK  = 320;
constexpr int WINF = 384;    // staged fea_r floats per channel (covers all taps incl. clamps)
constexpr int STR  = 400;    // padded stage stride in floats (LDS.128 overread safety)
constexpr int DEP  = 4;      // cp.async pipeline depth

__device__ __forceinline__ void cp16(uint32_t s, const void* g) {
    asm volatile("cp.async.cg.shared.global [%0], [%1], 16;\n" :: "r"(s), "l"(g) : "memory");
}
__device__ __forceinline__ void cp_commit() {
    asm volatile("cp.async.commit_group;" ::: "memory");
}
template<int N> __device__ __forceinline__ void cp_wait() {
    asm volatile("cp.async.wait_group %0;" :: "n"(N) : "memory");
}

__global__ __launch_bounds__(BLK)
void tile_warp_cost_kernel(const float* __restrict__ tile_plane,
                           const float* __restrict__ fea_l,
                           const float* __restrict__ fea_r,
                           float* __restrict__ out)
{
    __shared__ __align__(16) float ring[DEP][STR];

    const int tid = threadIdx.x;
    const int xb  = blockIdx.x * SEG;
    const int y   = blockIdx.y;
    const int b   = blockIdx.z;
    const int x   = xb + tid;

    const int ty = y >> 2, tx = x >> 2;
    const int iy = y & 3,  jx = x & 3;

    // tile_plane [B, 3, Ht, Wt]
    const int tb    = b * 3 * Ht * Wt + ty * Wt + tx;
    const float d   = __ldg(tile_plane + tb);
    const float ddx = __ldg(tile_plane + tb + Ht * Wt);
    const float ddy = __ldg(tile_plane + tb + 2 * Ht * Wt);

    const float disp0 = d + ((float)iy - 1.5f) * ddy + ((float)jx - 1.5f) * ddx;
    const float xs0   = (float)x - disp0;
    const float xf    = floorf(xs0);
    const float w     = xs0 - xf;
    const int   x00   = (int)xf;

    // clamped taps (always within the staged window for this block, see wb)
    const int j0 = min(max(x00 - 1, 0), W - 1);
    const int j1 = min(max(x00,     0), W - 1);
    const int j2 = min(max(x00 + 1, 0), W - 1);
    const int j3 = min(max(x00 + 2, 0), W - 1);

    // staged window base: covers [xb-56, xb+SEG+8) clipped to the row
    const int wb = min(max(xb - 56, 0), W - WINF);

    // natural path: taps unclamped AND window-covered -> vector LDS + select net
    const bool natv = (x00 >= 1) && (x00 + 2 <= W - 1) &&
                      (x00 - 1 >= wb) && (x00 + 2 < wb + WINF);
    // clamped but in-window (boundary pixels)
    const bool inw  = (j0 >= wb) && (j3 < wb + WINF);

    const int  o  = x00 - 1 - wb;     // window offset of tap 0 (natural path)
    const int  a4 = o & ~3;           // 16B-aligned granule
    const bool s2 = (o & 2) != 0;
    const bool s1 = (o & 1) != 0;

    const float* rowR = fea_r + ((size_t)(b * C) * H + y) * W;   // channel 0 row
    const float* pl   = fea_l + ((size_t)(b * C) * H + y) * W + x;

    const uint32_t sb0 = (uint32_t)__cvta_generic_to_shared(&ring[0][0]);

    // stage channel c's window: 384 floats = 96 lanes x 16B
    auto issue = [&](int c) {
        if (c < C && tid < 96)
            cp16(sb0 + (uint32_t)((c & (DEP - 1)) * STR + tid * 4) * 4,
                 rowR + (size_t)c * HW + wb + tid * 4);
        cp_commit();
    };

    issue(0); issue(1); issue(2);      // depth-3 prologue

    float fl = __ldg(pl);              // fea_l prefetch (channel 0)
    float cM = 0.f, c0a = 0.f, cP = 0.f, sA = 0.f;

    #pragma unroll 1
    for (int c = 0; c < C; ++c) {
        cp_wait<DEP - 2>();            // stage c landed (own shares)
        __syncthreads();               // all shares visible; prior reads retired
        issue(c + DEP - 1);            // refill slot freed at iter c-1

        const float flc = fl;
        if (c + 1 < C) fl = __ldg(pl + (size_t)(c + 1) * HW);

        const float* ws = ring[c & (DEP - 1)];
        float t0, t1, t2, t3;
        if (natv) {
            const float4 fa = *(const float4*)(ws + a4);
            const float4 fb = *(const float4*)(ws + a4 + 4);
            const float a0 = s2 ? fa.z : fa.x;
            const float a1 = s2 ? fa.w : fa.y;
            const float a2 = s2 ? fb.x : fa.z;
            const float a3 = s2 ? fb.y : fa.w;
            const float a4v = s2 ? fb.z : fb.x;
            t0 = s1 ? a1 : a0;
            t1 = s1 ? a2 : a1;
            t2 = s1 ? a3 : a2;
            t3 = s1 ? a4v : a3;
        } else if (inw) {              // boundary clamp, still served from smem
            t0 = ws[j0 - wb]; t1 = ws[j1 - wb];
            t2 = ws[j2 - wb]; t3 = ws[j3 - wb];
        } else {                       // pathological slope (never in practice)
            const float* rr = rowR + (size_t)c * HW;
            t0 = __ldg(rr + j0); t1 = __ldg(rr + j1);
            t2 = __ldg(rr + j2); t3 = __ldg(rr + j3);
        }

        const float hP = fmaf(w, t1 - t0, t0);   // disp_d = +1
        const float h0 = fmaf(w, t2 - t1, t1);   // disp_d =  0
        const float hM = fmaf(w, t3 - t2, t2);   // disp_d = -1
        cM  += fabsf(flc - hM);
        c0a += fabsf(flc - h0);
        cP  += fabsf(flc - hP);
        sA  += fabsf(flc);                       // invalid-hyp fallback
    }

    // per-pixel validity applied once
    const float wm1 = (float)(W - 1);
    if (!((xs0 + 1.0f >= 0.0f) && (xs0 + 1.0f <= wm1))) cM  = sA;  // disp_d = -1
    if (!((xs0        >= 0.0f) && (xs0        <= wm1))) c0a = sA;  // disp_d =  0
    if (!((xs0 - 1.0f >= 0.0f) && (xs0 - 1.0f <= wm1))) cP  = sA;  // disp_d = +1

    // output [B, 48, Ht, Wt]; channel = vblock*16 + iy*4 + jx; vblocks: -1, 0, +1
    const int chsp  = (iy * 4 + jx) * (Ht * Wt);
    const int obase = b * 48 * Ht * Wt + ty * Wt + tx;
    out[obase + chsp]                = cM;
    out[obase + 16 * Ht * Wt + chsp] = c0a;
    out[obase + 32 * Ht * Wt + chsp] = cP;
}

extern "C" void kernel_launch(void* const* d_in, const int* in_sizes, int n_in,
                              void* d_out, int out_size)
{
    const float* tile_plane = (const float*)d_in[0];
    const float* fea_l      = (const float*)d_in[1];
    const float* fea_r      = (const float*)d_in[2];
    float*       out        = (float*)d_out;

    dim3 grid(W / SEG, H, NB);   // (3, 512, 4)
    dim3 block(BLK);
    tile_warp_cost_kernel<<<grid, block>>>(tile_plane, fea_l, fea_r, out);
}

// round 15
// speedup vs baseline: 1.0613x; 1.0613x over previous
#include <cuda_runtime.h>

constexpr int NB = 4, C = 32, H = 512, W = 960, Ht = 128, Wt = 240, HW = H * W;
constexpr int BX  = 160;    // threads per block; each thread owns 2 adjacent px
constexpr int SEG = 2 * BX; // 320 px per block; 960 = 3*320
constexpr int UB  = 2;      // channel batch

__global__ __launch_bounds__(BX)
void tile_warp_cost_kernel(const float* __restrict__ tile_plane,
                           const float* __restrict__ fea_l,
                           const float* __restrict__ fea_r,
                           float* __restrict__ out)
{
    const int x  = blockIdx.x * SEG + 2 * threadIdx.x;  // even; owns x, x+1
    const int y  = blockIdx.y;
    const int b  = blockIdx.z;

    const int ty = y >> 2, tx = x >> 2;                 // same tile for both px
    const int iy = y & 3,  jx = x & 3;                  // jx in {0, 2}

    // tile_plane [B, 3, Ht, Wt]
    const int tb    = b * 3 * Ht * Wt + ty * Wt + tx;
    const float d   = __ldg(tile_plane + tb);
    const float ddx = __ldg(tile_plane + tb + Ht * Wt);
    const float ddy = __ldg(tile_plane + tb + 2 * Ht * Wt);

    // per-pixel (p = 0,1) slanted-plane source coords
    const float com  = d + ((float)iy - 1.5f) * ddy;
    float xs[2], wf[2];
    int   x00[2];
    #pragma unroll
    for (int p = 0; p < 2; ++p) {
        const float disp0 = com + ((float)(jx + p) - 1.5f) * ddx;
        xs[p] = (float)(x + p) - disp0;
        const float ff = floorf(xs[p]);
        wf[p]  = xs[p] - ff;
        x00[p] = (int)ff;
    }

    const int base  = x00[0] - 1;                 // 6-float window [base, base+5]
    const int delta = x00[1] - x00[0];
    const bool fastp = (base >= 0) && (base + 5 <= W - 1) && (delta >= 0) && (delta <= 2);
    const bool d0 = (delta == 0), d2 = (delta == 2);

    // clamped taps for the exact fallback path
    int jc[2][4];
    #pragma unroll
    for (int p = 0; p < 2; ++p) {
        jc[p][0] = min(max(x00[p] - 1, 0), W - 1);
        jc[p][1] = min(max(x00[p],     0), W - 1);
        jc[p][2] = min(max(x00[p] + 1, 0), W - 1);
        jc[p][3] = min(max(x00[p] + 2, 0), W - 1);
    }

    const float* pl = fea_l + ((size_t)(b * C) * H + y) * W + x;   // even -> 8B aligned
    const float* pr = fea_r + ((size_t)(b * C) * H + y) * W;

    float cM[2] = {0.f, 0.f}, c0[2] = {0.f, 0.f}, cP[2] = {0.f, 0.f}, sA[2] = {0.f, 0.f};

    #pragma unroll 1
    for (int cb = 0; cb < C; cb += UB) {
        float fl0[UB], fl1[UB], wv[UB][6];
        float t1v[UB][4];

        // ---- load phase ----
        #pragma unroll
        for (int u = 0; u < UB; ++u) {
            const float2 f2 = __ldg((const float2*)(pl + (size_t)u * HW));
            fl0[u] = f2.x; fl1[u] = f2.y;
            const float* rr = pr + (size_t)u * HW;
            if (fastp) {
                #pragma unroll
                for (int k = 0; k < 6; ++k) wv[u][k] = __ldg(rr + base + k);
            } else {
                #pragma unroll
                for (int k = 0; k < 4; ++k) wv[u][k]  = __ldg(rr + jc[0][k]);
                #pragma unroll
                for (int k = 0; k < 4; ++k) t1v[u][k] = __ldg(rr + jc[1][k]);
            }
        }

        // ---- compute phase ----
        #pragma unroll
        for (int u = 0; u < UB; ++u) {
            // pixel 0 taps = wv[0..3]
            {
                const float w  = wf[0];
                const float hP = fmaf(w, wv[u][1] - wv[u][0], wv[u][0]);
                const float h0 = fmaf(w, wv[u][2] - wv[u][1], wv[u][1]);
                const float hM = fmaf(w, wv[u][3] - wv[u][2], wv[u][2]);
                const float fl = fl0[u];
                cM[0] += fabsf(fl - hM);
                c0[0] += fabsf(fl - h0);
                cP[0] += fabsf(fl - hP);
                sA[0] += fabsf(fl);
            }
            // pixel 1 taps = wv[delta .. delta+3] (fast) or t1v (fallback)
            {
                float s0, s1, s2, s3;
                if (fastp) {
                    s0 = d0 ? wv[u][0] : (d2 ? wv[u][2] : wv[u][1]);
                    s1 = d0 ? wv[u][1] : (d2 ? wv[u][3] : wv[u][2]);
                    s2 = d0 ? wv[u][2] : (d2 ? wv[u][4] : wv[u][3]);
                    s3 = d0 ? wv[u][3] : (d2 ? wv[u][5] : wv[u][4]);
                } else {
                    s0 = t1v[u][0]; s1 = t1v[u][1]; s2 = t1v[u][2]; s3 = t1v[u][3];
                }
                const float w  = wf[1];
                const float hP = fmaf(w, s1 - s0, s0);
                const float h0 = fmaf(w, s2 - s1, s1);
                const float hM = fmaf(w, s3 - s2, s2);
                const float fl = fl1[u];
                cM[1] += fabsf(fl - hM);
                c0[1] += fabsf(fl - h0);
                cP[1] += fabsf(fl - hP);
                sA[1] += fabsf(fl);
            }
        }
        pl += (size_t)UB * HW;
        pr += (size_t)UB * HW;
    }

    // ---- epilogue: validity + stores  out[B, 48, Ht, Wt] ----
    const float wm1   = (float)(W - 1);
    const int  cplane = Ht * Wt;
    const int  obase  = b * 48 * cplane + ty * Wt + tx;
    #pragma unroll
    for (int p = 0; p < 2; ++p) {
        const bool vM = (xs[p] + 1.0f >= 0.0f) && (xs[p] + 1.0f <= wm1);
        const bool v0 = (xs[p]        >= 0.0f) && (xs[p]        <= wm1);
        const bool vP = (xs[p] - 1.0f >= 0.0f) && (xs[p] - 1.0f <= wm1);
        const float rM = vM ? cM[p] : sA[p];
        const float r0 = v0 ? c0[p] : sA[p];
        const float rP = vP ? cP[p] : sA[p];
        const int ch = iy * 4 + (jx + p);
        out[obase + ch * cplane]        = rM;   // hyp -1
        out[obase + (16 + ch) * cplane] = r0;   // hyp  0
        out[obase + (32 + ch) * cplane] = rP;   // hyp +1
    }
}

extern "C" void kernel_launch(void* const* d_in, const int* in_sizes, int n_in,
                              void* d_out, int out_size)
{
    const float* tile_plane = (const float*)d_in[0];
    const float* fea_l      = (const float*)d_in[1];
    const float* fea_r      = (const float*)d_in[2];
    float*       out        = (float*)d_out;

    dim3 grid(W / SEG, H, NB);   // (3, 512, 4)
    dim3 block(BX);
    tile_warp_cost_kernel<<<grid, block>>>(tile_plane, fea_l, fea_r, out);
}